// round 6
// baseline (speedup 1.0000x reference)
#include <cuda_runtime.h>
#include <cuda_bf16.h>
#include <cstdint>

// y_t = d*y_{t-1} + x_t   per channel, y_{-1} = 0  (so y_0 = x_0)
// x: [BSZ=8, SEQ=4096, CH=1024] fp32, d: [CH] fp32, out same shape as x.
//
// One block per (batch, 32-channel group) column = 256 blocks,
// 256 threads = NSUB(8) t-subtiles x 32 channels, 2 blocks/SM (regs capped
// at 128 by __launch_bounds__(256,2)).
//
// R6: TSUB back to 32 (chunk = 256 steps, only 16 chunks => 16 barriers per
// block, half of R5) while KEEPING 2 blocks/SM. Register budget holds by
// dropping the power table (serial f *= dc chain in the store loop is
// throughput-only and hidden by cross-warp interleaving). Per-warp MLP
// doubles to 32 outstanding LDGs. Streaming cache hints (__ldcs/__stcs)
// since x and y are touched exactly once.
//
// Cross-subtile combine: every warp redundantly scans the 8 subtile
// aggregates (multiplier d^32) from parity-double-buffered smem and keeps a
// replicated carry register -> ONE bar.sync per chunk, no warp-0 critical
// section.

#define BSZ    8
#define SEQ    4096
#define CH     1024
#define TSUB   32
#define NSUB   8
#define NTHR   (NSUB * 32)          // 256
#define CHUNK  (TSUB * NSUB)        // 256
#define NCHUNK (SEQ / CHUNK)        // 16
#define CGRPS  (CH / 32)            // 32 channel groups per batch

__global__ __launch_bounds__(NTHR, 2)
void cummulsum_kernel(const float* __restrict__ x,
                      const float* __restrict__ d,
                      float* __restrict__ y)
{
    __shared__ float subAgg[2][NSUB][32];   // double-buffered by chunk parity

    const int tid  = threadIdx.x;
    const int lane = tid & 31;
    const int s    = tid >> 5;          // subtile index 0..7
    const int b    = blockIdx.x >> 5;   // batch 0..7
    const int cg   = blockIdx.x & 31;   // channel group 0..31
    const int c    = cg * 32 + lane;    // channel

    const float dc = __ldg(d + c);
    // dT = dc^TSUB = dc^32 via 5 squarings
    float dT = dc * dc;   // ^2
    dT = dT * dT;         // ^4
    dT = dT * dT;         // ^8
    dT = dT * dT;         // ^16
    dT = dT * dT;         // ^32

    const size_t colBase = ((size_t)b * SEQ) * CH + (size_t)c;
    const float* xp = x + colBase + (size_t)(s * TSUB) * CH;
    float*       yp = y + colBase + (size_t)(s * TSUB) * CH;

    float carry = 0.0f;   // replicated per-warp running state (identical in all warps)

    float xa[TSUB];
    float xb[TSUB];

    // Prologue: load chunk 0 (streaming: data is single-use)
    #pragma unroll
    for (int i = 0; i < TSUB; i++) xa[i] = __ldcs(xp + (size_t)i * CH);

    for (int k = 0; k < NCHUNK; k++) {
        const int p = k & 1;

        // Prefetch next chunk; independent of everything below.
        const float* xpn = xp + (size_t)CHUNK * CH;
        if (k + 1 < NCHUNK) {
            #pragma unroll
            for (int i = 0; i < TSUB; i++) xb[i] = __ldcs(xpn + (size_t)i * CH);
        }

        // Local serial scan in place (zero initial condition)
        #pragma unroll
        for (int i = 1; i < TSUB; i++) xa[i] = fmaf(dc, xa[i - 1], xa[i]);

        subAgg[p][s][lane] = xa[TSUB - 1];
        __syncthreads();

        // Every warp redundantly scans all 8 aggregates; uses the prefix for
        // its own subtile and updates its private replicated carry.
        float P;                         // state entering subtile s
        {
            float r = carry;
            P = r;                       // valid if s == 0
            #pragma unroll
            for (int j = 0; j < NSUB; j++) {
                const float aggj = subAgg[p][j][lane];
                r = fmaf(dT, r, aggj);   // state entering subtile j+1
                if (j + 1 == s) P = r;
            }
            carry = r;                   // state entering next chunk
        }

        // Correction + store: y_i = ylocal_i + dc^(i+1) * P
        // (serial f chain: throughput-only, hidden by warp interleaving)
        float f = dc;
        #pragma unroll
        for (int i = 0; i < TSUB; i++) {
            __stcs(yp + (size_t)i * CH, fmaf(f, P, xa[i]));
            f *= dc;
        }

        // Rotate buffers
        #pragma unroll
        for (int i = 0; i < TSUB; i++) xa[i] = xb[i];

        xp += (size_t)CHUNK * CH;
        yp += (size_t)CHUNK * CH;
    }
}

extern "C" void kernel_launch(void* const* d_in, const int* in_sizes, int n_in,
                              void* d_out, int out_size)
{
    const float* x = (const float*)d_in[0];
    const float* d = (const float*)d_in[1];
    float*       y = (float*)d_out;
    (void)in_sizes; (void)n_in; (void)out_size;

    cummulsum_kernel<<<BSZ * CGRPS, NTHR>>>(x, d, y);
}